// round 1
// baseline (speedup 1.0000x reference)
#include <cuda_runtime.h>
#include <cstdint>
#include <cstddef>

#define BB 16
#define MM 32
#define A_TOTAL 21824
#define NUM_FG 80
#define EPSF 1e-6f
#define BA (BB*A_TOTAL)
#define FULLM 0xFFFFFFFFu

__device__ unsigned int g_posmask[BA];
__device__ int g_lab[BA];
__device__ double g_acc[4];
__device__ int g_fgcnt;

__constant__ int c_lstart[5] = {0, 16384, 20480, 21504, 21760};
__constant__ int c_lsize[5]  = {16384, 4096, 1024, 256, 64};

// ---------------------------------------------------------------- init
__global__ void k_init() {
    int i = blockIdx.x * blockDim.x + threadIdx.x;
    if (i < BA) g_posmask[i] = 0u;
    if (i == 0) {
        g_acc[0] = 0.0; g_acc[1] = 0.0; g_acc[2] = 0.0; g_acc[3] = 0.0;
        g_fgcnt = 0;
    }
}

// ---------------------------------------------------------------- assignment
// One warp per (b, g) task. Top-9 smallest center-distances per level (45
// candidates), adaptive IoU threshold (mean + std ddof=1), center-inside test,
// scatter positives as bit g into g_posmask[b*A + anchor].
__global__ void k_assign(const float* __restrict__ anchors,
                         const float* __restrict__ gt) {
    int warp_id = (blockIdx.x * blockDim.x + threadIdx.x) >> 5;
    int lane = threadIdx.x & 31;
    int w = threadIdx.x >> 5;
    if (warp_id >= BB * MM) return;
    int b = warp_id >> 5;   // MM == 32
    int g = warp_id & 31;

    const float* gp = gt + (size_t)(b * MM + g) * 5;
    float lab = gp[4];
    if (lab <= 0.f) return;   // invalid gt: contributes no positives

    float gx1 = gp[0], gy1 = gp[1], gx2 = gp[2], gy2 = gp[3];
    float gcx = 0.5f * (gx1 + gx2), gcy = 0.5f * (gy1 + gy2);
    float garea = (gx2 - gx1) * (gy2 - gy1);

    __shared__ unsigned long long s_keys[8][288];
    __shared__ int s_cand[8][48];
    unsigned long long* keys = s_keys[w];
    int* cand = s_cand[w];

    int ncand = 0;
    for (int lvl = 0; lvl < 5; ++lvl) {
        int start = c_lstart[lvl], n = c_lsize[lvl];
        // per-lane sorted top-9 (key = dist2 bits << 32 | anchor idx; ties -> lower idx)
        unsigned long long t[9];
        #pragma unroll
        for (int k = 0; k < 9; ++k) t[k] = ~0ull;
        for (int i = lane; i < n; i += 32) {
            int ai = start + i;
            float4 av = ((const float4*)anchors)[ai];
            float acx = 0.5f * (av.x + av.z), acy = 0.5f * (av.y + av.w);
            float dx = acx - gcx, dy = acy - gcy;
            float d2 = dx * dx + dy * dy;
            unsigned long long key =
                (((unsigned long long)__float_as_uint(d2)) << 32) | (unsigned)ai;
            if (key < t[8]) {
                #pragma unroll
                for (int k = 0; k < 9; ++k) {
                    if (key < t[k]) { unsigned long long tmp = t[k]; t[k] = key; key = tmp; }
                }
            }
        }
        #pragma unroll
        for (int k = 0; k < 9; ++k) keys[lane * 9 + k] = t[k];
        __syncwarp();
        // 9 rounds of warp argmin over the 288 shared entries
        for (int r = 0; r < 9; ++r) {
            unsigned long long mn = ~0ull;
            #pragma unroll
            for (int j = 0; j < 9; ++j) {
                unsigned long long v = keys[lane + 32 * j];
                if (v < mn) mn = v;
            }
            #pragma unroll
            for (int off = 16; off; off >>= 1) {
                unsigned long long o = __shfl_xor_sync(FULLM, mn, off);
                if (o < mn) mn = o;
            }
            #pragma unroll
            for (int j = 0; j < 9; ++j)
                if (keys[lane + 32 * j] == mn) keys[lane + 32 * j] = ~0ull;
            if (lane == 0) cand[ncand + r] = (int)(unsigned)(mn & 0xFFFFFFFFu);
            __syncwarp();
        }
        ncand += 9;
    }
    __syncwarp();

    // candidate IoU + adaptive threshold (two-pass std, ddof=1)
    float myiou[2]; int mycand[2]; bool myin[2];
    float sum = 0.f;
    #pragma unroll
    for (int j = 0; j < 2; ++j) {
        int c = lane + 32 * j;
        myiou[j] = 0.f; mycand[j] = -1; myin[j] = false;
        if (c < 45) {
            int ai = cand[c];
            float4 av = ((const float4*)anchors)[ai];
            float iw = fmaxf(fminf(av.z, gx2) - fmaxf(av.x, gx1), 0.f);
            float ih = fmaxf(fminf(av.w, gy2) - fmaxf(av.y, gy1), 0.f);
            float inter = iw * ih;
            float aarea = (av.z - av.x) * (av.w - av.y);
            float uni = fmaxf(aarea + garea - inter, EPSF);
            float iou = inter / uni;
            float acx = 0.5f * (av.x + av.z), acy = 0.5f * (av.y + av.w);
            float l = acx - gx1, tt = acy - gy1, r = gx2 - acx, bb = gy2 - acy;
            myin[j] = fminf(fminf(l, r), fminf(tt, bb)) > 0.01f;
            myiou[j] = iou; mycand[j] = ai;
            sum += iou;
        }
    }
    #pragma unroll
    for (int off = 16; off; off >>= 1) sum += __shfl_xor_sync(FULLM, sum, off);
    float mean = sum * (1.f / 45.f);
    float dsum = 0.f;
    #pragma unroll
    for (int j = 0; j < 2; ++j) {
        if (mycand[j] >= 0) { float d = myiou[j] - mean; dsum += d * d; }
    }
    #pragma unroll
    for (int off = 16; off; off >>= 1) dsum += __shfl_xor_sync(FULLM, dsum, off);
    float thr = mean + sqrtf(fmaxf(dsum * (1.f / 44.f), 0.f));

    #pragma unroll
    for (int j = 0; j < 2; ++j) {
        if (mycand[j] >= 0 && myin[j] && myiou[j] >= thr) {
            atomicOr(&g_posmask[b * A_TOTAL + mycand[j]], 1u << g);
        }
    }
}

// ---------------------------------------------------------------- per-anchor
// Resolve best gt (argmax IoU, first-max wins), write label, and compute the
// fg-masked reg/ctn/jsd losses inline (pred_reg/pred_ctn only read when fg).
__global__ void k_best(const float* __restrict__ anchors,
                       const float* __restrict__ gt,
                       const float* __restrict__ pred_reg,
                       const float* __restrict__ pred_ctn) {
    int idx = blockIdx.x * blockDim.x + threadIdx.x;
    float lreg = 0.f, lctn = 0.f, ljsd = 0.f;
    int fg = 0;
    if (idx < BA) {
        int b = idx / A_TOTAL;
        int a = idx - b * A_TOTAL;
        unsigned mask = g_posmask[idx];
        int code = 0;
        if (mask) {
            fg = 1;
            float4 av = ((const float4*)anchors)[a];
            float best = -1.f; int bg = 0;
            unsigned m = mask;
            while (m) {
                int gg = __ffs(m) - 1; m &= (m - 1);
                const float* gp = gt + (size_t)(b * MM + gg) * 5;
                float gx1 = gp[0], gy1 = gp[1], gx2 = gp[2], gy2 = gp[3];
                float iw = fmaxf(fminf(av.z, gx2) - fmaxf(av.x, gx1), 0.f);
                float ih = fmaxf(fminf(av.w, gy2) - fmaxf(av.y, gy1), 0.f);
                float inter = iw * ih;
                float uni = fmaxf((av.z - av.x) * (av.w - av.y) +
                                  (gx2 - gx1) * (gy2 - gy1) - inter, EPSF);
                float iou = inter / uni;
                if (iou > best) { best = iou; bg = gg; }
            }
            const float* gp = gt + (size_t)(b * MM + bg) * 5;
            float gx1 = gp[0], gy1 = gp[1], gx2 = gp[2], gy2 = gp[3];
            code = (int)gp[4];

            float aw = av.z - av.x, ah = av.w - av.y;
            float ax = 0.5f * (av.x + av.z), ay = 0.5f * (av.y + av.w);
            float gw = fmaxf(gx2 - gx1, EPSF), gh = fmaxf(gy2 - gy1, EPSF);
            float gcx = 0.5f * (gx1 + gx2), gcy = 0.5f * (gy1 + gy2);
            float t0 = (gcx - ax) / aw, t1 = (gcy - ay) / ah;
            float t2 = __logf(gw / aw), t3 = __logf(gh / ah);

            // tbox = decode(encode(gt), anchor)
            float tcx = ax + t0 * aw, tcy = ay + t1 * ah;
            float tw = __expf(fminf(fmaxf(t2, -4.f), 4.f)) * aw;
            float th = __expf(fminf(fmaxf(t3, -4.f), 4.f)) * ah;
            float tx1 = tcx - 0.5f * tw, ty1 = tcy - 0.5f * th;
            float tx2 = tcx + 0.5f * tw, ty2 = tcy + 0.5f * th;

            // pbox
            const float4* prp = (const float4*)(pred_reg + (size_t)idx * 8);
            float4 mu = prp[0], ls = prp[1];
            float pcx = ax + mu.x * aw, pcy = ay + mu.y * ah;
            float pw = __expf(fminf(fmaxf(mu.z, -4.f), 4.f)) * aw;
            float ph = __expf(fminf(fmaxf(mu.w, -4.f), 4.f)) * ah;
            float px1 = pcx - 0.5f * pw, py1 = pcy - 0.5f * ph;
            float px2 = pcx + 0.5f * pw, py2 = pcy + 0.5f * ph;

            // giou loss
            float iw2 = fmaxf(fminf(px2, tx2) - fmaxf(px1, tx1), 0.f);
            float ih2 = fmaxf(fminf(py2, ty2) - fmaxf(py1, ty1), 0.f);
            float inter2 = iw2 * ih2;
            float a1 = (px2 - px1) * (py2 - py1);
            float a2 = (tx2 - tx1) * (ty2 - ty1);
            float uni2 = fmaxf(a1 + a2 - inter2, EPSF);
            float iou2 = inter2 / uni2;
            float ew = fmaxf(fmaxf(px2, tx2) - fminf(px1, tx1), 0.f);
            float eh = fmaxf(fmaxf(py2, ty2) - fminf(py1, ty1), 0.f);
            float enc = fmaxf(ew * eh, EPSF);
            lreg = 1.f - (iou2 - (enc - uni2) / enc);

            // centerness bce
            float cl = fmaxf(ax - tx1, EPSF), cr = fmaxf(tx2 - ax, EPSF);
            float ct = fmaxf(ay - ty1, EPSF), cb = fmaxf(ty2 - ay, EPSF);
            float ratio = (fminf(cl, cr) / fmaxf(cl, cr)) *
                          (fminf(ct, cb) / fmaxf(ct, cb));
            float ctn = sqrtf(fminf(fmaxf(ratio, EPSF), 1.f));
            float lg = pred_ctn[idx];
            lctn = fmaxf(lg, 0.f) - lg * ctn + log1pf(__expf(-fabsf(lg)));

            // jsd
            float mus[4] = {mu.x, mu.y, mu.z, mu.w};
            float lss[4] = {ls.x, ls.y, ls.z, ls.w};
            float ts[4]  = {t0, t1, t2, t3};
            float s = 0.f;
            #pragma unroll
            for (int k = 0; k < 4; ++k) {
                float var = __expf(2.f * lss[k]);
                float dd = mus[k] - ts[k]; dd *= dd;
                s += 0.5f * (var + dd) + (1.f + dd) * 0.5f / var - 1.f;
            }
            ljsd = 0.5f * s * 0.1f;
        }
        g_lab[idx] = code;
    }
    // block reduce -> one double atomic per block
    #pragma unroll
    for (int off = 16; off; off >>= 1) {
        lreg += __shfl_xor_sync(FULLM, lreg, off);
        lctn += __shfl_xor_sync(FULLM, lctn, off);
        ljsd += __shfl_xor_sync(FULLM, ljsd, off);
        fg   += __shfl_xor_sync(FULLM, fg, off);
    }
    __shared__ float s_r[3][8];
    __shared__ int s_f[8];
    int w = threadIdx.x >> 5, lane = threadIdx.x & 31;
    if (lane == 0) { s_r[0][w] = lreg; s_r[1][w] = lctn; s_r[2][w] = ljsd; s_f[w] = fg; }
    __syncthreads();
    if (threadIdx.x == 0) {
        float r = 0.f, c = 0.f, j = 0.f; int f = 0;
        #pragma unroll
        for (int k = 0; k < 8; ++k) { r += s_r[0][k]; c += s_r[1][k]; j += s_r[2][k]; f += s_f[k]; }
        if (f) {
            atomicAdd(&g_acc[1], (double)r);
            atomicAdd(&g_acc[2], (double)c);
            atomicAdd(&g_acc[3], (double)j);
            atomicAdd(&g_fgcnt, f);
        }
    }
}

// ---------------------------------------------------------------- focal cls
// ln p = -softplus(-x), ln(1-p) = -softplus(x); gamma=2 -> just squares.
__global__ void k_cls(const float* __restrict__ pred_cls) {
    const int NV = BA * 20;   // float4 count (80 floats / row)
    float facc = 0.f;
    for (int i = blockIdx.x * blockDim.x + threadIdx.x; i < NV;
         i += gridDim.x * blockDim.x) {
        float4 v = __ldg(((const float4*)pred_cls) + i);
        int row = i / 20;
        int tgt = g_lab[row] - 1;          // -1 when background -> never matches
        int c0 = (i - row * 20) * 4;
        float xs[4] = {v.x, v.y, v.z, v.w};
        #pragma unroll
        for (int j = 0; j < 4; ++j) {
            float x = xs[j];
            float aa = fabsf(x);
            float em = __expf(-aa);
            float lp = __logf(1.f + em);
            float r = __fdividef(1.f, 1.f + em);
            float p = (x >= 0.f) ? r : em * r;
            float q = 1.f - p;
            float term = ((c0 + j) == tgt)
                ? 0.25f * q * q * (fmaxf(-x, 0.f) + lp)
                : 0.75f * p * p * (fmaxf(x, 0.f) + lp);
            facc += term;
        }
    }
    #pragma unroll
    for (int off = 16; off; off >>= 1) facc += __shfl_xor_sync(FULLM, facc, off);
    __shared__ float sh[8];
    int w = threadIdx.x >> 5, lane = threadIdx.x & 31;
    if (lane == 0) sh[w] = facc;
    __syncthreads();
    if (threadIdx.x == 0) {
        float t = 0.f;
        #pragma unroll
        for (int k = 0; k < 8; ++k) t += sh[k];
        atomicAdd(&g_acc[0], (double)t);
    }
}

// ---------------------------------------------------------------- finalize
__global__ void k_final(float* __restrict__ out) {
    if (threadIdx.x == 0 && blockIdx.x == 0) {
        float fg = (float)g_fgcnt;
        float ln = 0.9f * 100.f + 0.1f * fmaxf(fg, 1.f);
        out[0] = (float)(g_acc[0] / (double)ln);
        out[1] = (float)(g_acc[1] / (double)ln);
        out[2] = (float)(g_acc[2] / (double)ln);
        out[3] = (float)(g_acc[3] / (double)ln);
    }
}

extern "C" void kernel_launch(void* const* d_in, const int* in_sizes, int n_in,
                              void* d_out, int out_size) {
    const float* pred_cls = (const float*)d_in[0];
    const float* pred_reg = (const float*)d_in[1];
    const float* pred_ctn = (const float*)d_in[2];
    const float* anchors  = (const float*)d_in[3];
    const float* gt       = (const float*)d_in[4];
    (void)in_sizes; (void)n_in; (void)out_size;

    k_init<<<(BA + 255) / 256, 256>>>();
    k_assign<<<64, 256>>>(anchors, gt);
    k_best<<<(BA + 255) / 256, 256>>>(anchors, gt, pred_reg, pred_ctn);
    k_cls<<<2048, 256>>>(pred_cls);
    k_final<<<1, 32>>>((float*)d_out);
}

// round 2
// speedup vs baseline: 4.4097x; 4.4097x over previous
#include <cuda_runtime.h>
#include <cstdint>
#include <cstddef>

#define BB 16
#define MM 32
#define A_TOTAL 21824
#define NUM_FG 80
#define EPSF 1e-6f
#define BA (BB*A_TOTAL)
#define FULLM 0xFFFFFFFFu

__device__ unsigned int g_posmask[BA];
__device__ double g_acc[4];
__device__ int g_fgcnt;

__constant__ int   c_lstart[5] = {0, 16384, 20480, 21504, 21760};
__constant__ int   c_feat[5]   = {128, 64, 32, 16, 8};
__constant__ float c_strf[5]   = {8.f, 16.f, 32.f, 64.f, 128.f};
__constant__ float c_invs[5]   = {0.125f, 0.0625f, 0.03125f, 0.015625f, 0.0078125f};

// ---------------------------------------------------------------- init
__global__ void k_init() {
    int i = blockIdx.x * blockDim.x + threadIdx.x;
    if (i < BA) g_posmask[i] = 0u;
    if (i == 0) {
        g_acc[0] = 0.0; g_acc[1] = 0.0; g_acc[2] = 0.0; g_acc[3] = 0.0;
        g_fgcnt = 0;
    }
}

// ---------------------------------------------------------------- assignment
// One warp per (b, g). Anchors form a regular grid per level, so the 9
// nearest centers lie inside the 5x5 window around the containing cell
// (the 3x3 block gives 9 points within 2.12*s; anything outside the 5x5 is
// >= 2.5*s away). 25 exact distances -> 9 warp-argmin rounds (key = d2
// bits << 32 | anchor idx, matching jax top_k tie order). Then the usual
// adaptive-threshold IoU test over the 45 candidates.
__global__ void k_assign(const float* __restrict__ anchors,
                         const float* __restrict__ gt) {
    int warp_id = (blockIdx.x * blockDim.x + threadIdx.x) >> 5;
    int lane = threadIdx.x & 31;
    int w = threadIdx.x >> 5;
    __shared__ int s_cand[8][48];
    if (warp_id >= BB * MM) return;
    int b = warp_id >> 5;   // MM == 32
    int g = warp_id & 31;

    const float* gp = gt + (size_t)(b * MM + g) * 5;
    if (gp[4] <= 0.f) return;   // invalid gt

    float gx1 = gp[0], gy1 = gp[1], gx2 = gp[2], gy2 = gp[3];
    float gcx = 0.5f * (gx1 + gx2), gcy = 0.5f * (gy1 + gy2);
    float garea = (gx2 - gx1) * (gy2 - gy1);

    int* cand = s_cand[w];

    #pragma unroll
    for (int lvl = 0; lvl < 5; ++lvl) {
        float s = c_strf[lvl], inv = c_invs[lvl];
        int f = c_feat[lvl], start = c_lstart[lvl];
        int ix = (int)floorf(gcx * inv);
        int iy = (int)floorf(gcy * inv);
        int x0 = min(max(ix - 2, 0), f - 5);
        int y0 = min(max(iy - 2, 0), f - 5);
        unsigned long long key = ~0ull;
        if (lane < 25) {
            int cx = x0 + (lane % 5);
            int cy = y0 + (lane / 5);
            float acx = ((float)cx + 0.5f) * s;
            float acy = ((float)cy + 0.5f) * s;
            float dx = acx - gcx, dy = acy - gcy;
            float d2 = dx * dx + dy * dy;
            int ai = start + cy * f + cx;
            key = (((unsigned long long)__float_as_uint(d2)) << 32) | (unsigned)ai;
        }
        #pragma unroll
        for (int r = 0; r < 9; ++r) {
            unsigned long long mn = key;
            #pragma unroll
            for (int off = 16; off; off >>= 1) {
                unsigned long long o = __shfl_xor_sync(FULLM, mn, off);
                if (o < mn) mn = o;
            }
            if (key == mn) key = ~0ull;
            if (lane == 0) cand[lvl * 9 + r] = (int)(unsigned)(mn & 0xFFFFFFFFu);
        }
    }
    __syncwarp();

    // candidate IoU + adaptive threshold (two-pass std, ddof=1)
    float myiou[2]; int mycand[2]; bool myin[2];
    float sum = 0.f;
    #pragma unroll
    for (int j = 0; j < 2; ++j) {
        int c = lane + 32 * j;
        myiou[j] = 0.f; mycand[j] = -1; myin[j] = false;
        if (c < 45) {
            int ai = cand[c];
            float4 av = ((const float4*)anchors)[ai];
            float iw = fmaxf(fminf(av.z, gx2) - fmaxf(av.x, gx1), 0.f);
            float ih = fmaxf(fminf(av.w, gy2) - fmaxf(av.y, gy1), 0.f);
            float inter = iw * ih;
            float aarea = (av.z - av.x) * (av.w - av.y);
            float uni = fmaxf(aarea + garea - inter, EPSF);
            float iou = inter / uni;
            float acx = 0.5f * (av.x + av.z), acy = 0.5f * (av.y + av.w);
            float l = acx - gx1, tt = acy - gy1, r = gx2 - acx, bb = gy2 - acy;
            myin[j] = fminf(fminf(l, r), fminf(tt, bb)) > 0.01f;
            myiou[j] = iou; mycand[j] = ai;
            sum += iou;
        }
    }
    #pragma unroll
    for (int off = 16; off; off >>= 1) sum += __shfl_xor_sync(FULLM, sum, off);
    float mean = sum * (1.f / 45.f);
    float dsum = 0.f;
    #pragma unroll
    for (int j = 0; j < 2; ++j) {
        if (mycand[j] >= 0) { float d = myiou[j] - mean; dsum += d * d; }
    }
    #pragma unroll
    for (int off = 16; off; off >>= 1) dsum += __shfl_xor_sync(FULLM, dsum, off);
    float thr = mean + sqrtf(fmaxf(dsum * (1.f / 44.f), 0.f));

    #pragma unroll
    for (int j = 0; j < 2; ++j) {
        if (mycand[j] >= 0 && myin[j] && myiou[j] >= thr) {
            atomicOr(&g_posmask[b * A_TOTAL + mycand[j]], 1u << g);
        }
    }
}

// ---------------------------------------------------------------- per-anchor
// Resolve best gt (argmax IoU), compute reg/ctn/jsd losses for fg anchors,
// plus the focal-loss CORRECTION for the single target class:
//   corr = pos(x_t) - neg(x_t)   (k_cls sums neg() over everything).
__global__ void k_best(const float* __restrict__ anchors,
                       const float* __restrict__ gt,
                       const float* __restrict__ pred_reg,
                       const float* __restrict__ pred_ctn,
                       const float* __restrict__ pred_cls) {
    int idx = blockIdx.x * blockDim.x + threadIdx.x;
    float lreg = 0.f, lctn = 0.f, ljsd = 0.f, lcls = 0.f;
    int fg = 0;
    if (idx < BA) {
        int b = idx / A_TOTAL;
        int a = idx - b * A_TOTAL;
        unsigned mask = g_posmask[idx];
        if (mask) {
            fg = 1;
            float4 av = ((const float4*)anchors)[a];
            float best = -1.f; int bg = 0;
            unsigned m = mask;
            while (m) {
                int gg = __ffs(m) - 1; m &= (m - 1);
                const float* gp = gt + (size_t)(b * MM + gg) * 5;
                float gx1 = gp[0], gy1 = gp[1], gx2 = gp[2], gy2 = gp[3];
                float iw = fmaxf(fminf(av.z, gx2) - fmaxf(av.x, gx1), 0.f);
                float ih = fmaxf(fminf(av.w, gy2) - fmaxf(av.y, gy1), 0.f);
                float inter = iw * ih;
                float uni = fmaxf((av.z - av.x) * (av.w - av.y) +
                                  (gx2 - gx1) * (gy2 - gy1) - inter, EPSF);
                float iou = inter / uni;
                if (iou > best) { best = iou; bg = gg; }
            }
            const float* gp = gt + (size_t)(b * MM + bg) * 5;
            float gx1 = gp[0], gy1 = gp[1], gx2 = gp[2], gy2 = gp[3];
            int tgt = (int)gp[4] - 1;

            float aw = av.z - av.x, ah = av.w - av.y;
            float ax = 0.5f * (av.x + av.z), ay = 0.5f * (av.y + av.w);
            float gw = fmaxf(gx2 - gx1, EPSF), gh = fmaxf(gy2 - gy1, EPSF);
            float gcx = 0.5f * (gx1 + gx2), gcy = 0.5f * (gy1 + gy2);
            float t0 = (gcx - ax) / aw, t1 = (gcy - ay) / ah;
            float t2 = __logf(gw / aw), t3 = __logf(gh / ah);

            // tbox = decode(encode(gt), anchor)
            float tcx = ax + t0 * aw, tcy = ay + t1 * ah;
            float tw = __expf(fminf(fmaxf(t2, -4.f), 4.f)) * aw;
            float th = __expf(fminf(fmaxf(t3, -4.f), 4.f)) * ah;
            float tx1 = tcx - 0.5f * tw, ty1 = tcy - 0.5f * th;
            float tx2 = tcx + 0.5f * tw, ty2 = tcy + 0.5f * th;

            // pbox
            const float4* prp = (const float4*)(pred_reg + (size_t)idx * 8);
            float4 mu = prp[0], ls = prp[1];
            float pcx = ax + mu.x * aw, pcy = ay + mu.y * ah;
            float pw = __expf(fminf(fmaxf(mu.z, -4.f), 4.f)) * aw;
            float ph = __expf(fminf(fmaxf(mu.w, -4.f), 4.f)) * ah;
            float px1 = pcx - 0.5f * pw, py1 = pcy - 0.5f * ph;
            float px2 = pcx + 0.5f * pw, py2 = pcy + 0.5f * ph;

            // giou loss
            float iw2 = fmaxf(fminf(px2, tx2) - fmaxf(px1, tx1), 0.f);
            float ih2 = fmaxf(fminf(py2, ty2) - fmaxf(py1, ty1), 0.f);
            float inter2 = iw2 * ih2;
            float a1 = (px2 - px1) * (py2 - py1);
            float a2 = (tx2 - tx1) * (ty2 - ty1);
            float uni2 = fmaxf(a1 + a2 - inter2, EPSF);
            float iou2 = inter2 / uni2;
            float ew = fmaxf(fmaxf(px2, tx2) - fminf(px1, tx1), 0.f);
            float eh = fmaxf(fmaxf(py2, ty2) - fminf(py1, ty1), 0.f);
            float enc = fmaxf(ew * eh, EPSF);
            lreg = 1.f - (iou2 - (enc - uni2) / enc);

            // centerness bce
            float cl = fmaxf(ax - tx1, EPSF), cr = fmaxf(tx2 - ax, EPSF);
            float ct = fmaxf(ay - ty1, EPSF), cb = fmaxf(ty2 - ay, EPSF);
            float ratio = (fminf(cl, cr) / fmaxf(cl, cr)) *
                          (fminf(ct, cb) / fmaxf(ct, cb));
            float ctn = sqrtf(fminf(fmaxf(ratio, EPSF), 1.f));
            float lg = pred_ctn[idx];
            lctn = fmaxf(lg, 0.f) - lg * ctn + log1pf(__expf(-fabsf(lg)));

            // jsd
            float mus[4] = {mu.x, mu.y, mu.z, mu.w};
            float lss[4] = {ls.x, ls.y, ls.z, ls.w};
            float ts[4]  = {t0, t1, t2, t3};
            float s = 0.f;
            #pragma unroll
            for (int k = 0; k < 4; ++k) {
                float var = __expf(2.f * lss[k]);
                float dd = mus[k] - ts[k]; dd *= dd;
                s += 0.5f * (var + dd) + (1.f + dd) * 0.5f / var - 1.f;
            }
            ljsd = 0.5f * s * 0.1f;

            // focal correction for the target class
            float x = pred_cls[(size_t)idx * NUM_FG + tgt];
            float u = __expf(-fabsf(x));
            float lp = log1pf(u);
            float r = __fdividef(1.f, 1.f + u);
            float p = (x >= 0.f) ? r : u * r;
            float q = 1.f - p;
            float pos = 0.25f * q * q * (fmaxf(-x, 0.f) + lp);
            float neg = 0.75f * p * p * (fmaxf(x, 0.f) + lp);
            lcls = pos - neg;
        }
    }
    // block reduce -> one double atomic per block
    #pragma unroll
    for (int off = 16; off; off >>= 1) {
        lreg += __shfl_xor_sync(FULLM, lreg, off);
        lctn += __shfl_xor_sync(FULLM, lctn, off);
        ljsd += __shfl_xor_sync(FULLM, ljsd, off);
        lcls += __shfl_xor_sync(FULLM, lcls, off);
        fg   += __shfl_xor_sync(FULLM, fg, off);
    }
    __shared__ float s_r[4][8];
    __shared__ int s_f[8];
    int w = threadIdx.x >> 5, lane = threadIdx.x & 31;
    if (lane == 0) {
        s_r[0][w] = lreg; s_r[1][w] = lctn; s_r[2][w] = ljsd; s_r[3][w] = lcls;
        s_f[w] = fg;
    }
    __syncthreads();
    if (threadIdx.x == 0) {
        float r = 0.f, c = 0.f, j = 0.f, cl = 0.f; int f = 0;
        #pragma unroll
        for (int k = 0; k < 8; ++k) {
            r += s_r[0][k]; c += s_r[1][k]; j += s_r[2][k]; cl += s_r[3][k];
            f += s_f[k];
        }
        if (f) {
            atomicAdd(&g_acc[0], (double)cl);
            atomicAdd(&g_acc[1], (double)r);
            atomicAdd(&g_acc[2], (double)c);
            atomicAdd(&g_acc[3], (double)j);
            atomicAdd(&g_fgcnt, f);
        }
    }
}

// ---------------------------------------------------------------- focal cls
// Pure stream: sum the BACKGROUND focal term over every (row, class).
// neg(x) = 0.75 * sigmoid(x)^2 * softplus(x), softplus(x) = x + ln(1+e^-x).
// The per-target-class correction is applied in k_best.
__global__ void k_cls(const float* __restrict__ pred_cls) {
    const int NV = BA * 20;   // float4 count (80 floats / row)
    float facc = 0.f;
    for (int i = blockIdx.x * blockDim.x + threadIdx.x; i < NV;
         i += gridDim.x * blockDim.x) {
        float4 v = __ldg(((const float4*)pred_cls) + i);
        float xs[4] = {v.x, v.y, v.z, v.w};
        #pragma unroll
        for (int j = 0; j < 4; ++j) {
            float x = xs[j];
            float u = __expf(-x);
            float d = 1.f + u;
            float r = __fdividef(1.f, d);   // sigmoid(x)
            float sp = x + __logf(d);       // softplus(x)
            facc = fmaf(0.75f * r * r, sp, facc);
        }
    }
    #pragma unroll
    for (int off = 16; off; off >>= 1) facc += __shfl_xor_sync(FULLM, facc, off);
    __shared__ float sh[8];
    int w = threadIdx.x >> 5, lane = threadIdx.x & 31;
    if (lane == 0) sh[w] = facc;
    __syncthreads();
    if (threadIdx.x == 0) {
        float t = 0.f;
        #pragma unroll
        for (int k = 0; k < 8; ++k) t += sh[k];
        atomicAdd(&g_acc[0], (double)t);
    }
}

// ---------------------------------------------------------------- finalize
__global__ void k_final(float* __restrict__ out) {
    if (threadIdx.x == 0 && blockIdx.x == 0) {
        float fg = (float)g_fgcnt;
        float ln = 0.9f * 100.f + 0.1f * fmaxf(fg, 1.f);
        out[0] = (float)(g_acc[0] / (double)ln);
        out[1] = (float)(g_acc[1] / (double)ln);
        out[2] = (float)(g_acc[2] / (double)ln);
        out[3] = (float)(g_acc[3] / (double)ln);
    }
}

extern "C" void kernel_launch(void* const* d_in, const int* in_sizes, int n_in,
                              void* d_out, int out_size) {
    const float* pred_cls = (const float*)d_in[0];
    const float* pred_reg = (const float*)d_in[1];
    const float* pred_ctn = (const float*)d_in[2];
    const float* anchors  = (const float*)d_in[3];
    const float* gt       = (const float*)d_in[4];
    (void)in_sizes; (void)n_in; (void)out_size;

    k_init<<<(BA + 255) / 256, 256>>>();
    k_cls<<<2048, 256>>>(pred_cls);
    k_assign<<<64, 256>>>(anchors, gt);
    k_best<<<(BA + 255) / 256, 256>>>(anchors, gt, pred_reg, pred_ctn, pred_cls);
    k_final<<<1, 32>>>((float*)d_out);
}